// round 11
// baseline (speedup 1.0000x reference)
#include <cuda_runtime.h>
#include <cuda_bf16.h>

#define BB   64
#define SS   512
#define KRAW 850
#define KPAD 864
#define HID  512
#define G4   2048
#define MTOT (BB * SS)

// ---------------- scratch (static device globals; no runtime alloc) ----------
__device__ __align__(16) float g_catL[(size_t)MTOT * KPAD];
__device__ __align__(16) float g_catR[(size_t)MTOT * KPAD];
__device__ __align__(16) float g_Wpad[(size_t)HID * KPAD];
__device__ __align__(16) float g_WihL[(size_t)G4 * HID];
__device__ __align__(16) float g_WihR[(size_t)G4 * HID];
__device__ __align__(16) float g_inL[(size_t)MTOT * HID];
__device__ __align__(16) float g_inR[(size_t)MTOT * HID];
__device__ __align__(16) float g_xgL[(size_t)MTOT * G4];   // [S][B][2048]
__device__ __align__(16) float g_xgR[(size_t)MTOT * G4];
// h double buffer, bf16, m16n8k16 A-fragment packed (see lstm_kernel)
__device__ __align__(16) __nv_bfloat16 g_hbf[2][2][BB * HID];
__device__ unsigned g_cnt[2];                  // per-direction step counter

__device__ __forceinline__ float tanha(float x) {
    float r;
    asm("tanh.approx.f32 %0, %1;" : "=f"(r) : "f"(x));
    return r;
}
__device__ __forceinline__ float siga(float x) {
    return fmaf(0.5f, tanha(0.5f * x), 0.5f);
}
__device__ __forceinline__ float to_tf32(float x) {
    float r;
    asm("cvt.rna.tf32.f32 %0, %1;" : "=f"(r) : "f"(x));
    return r;
}
__device__ __forceinline__ float4 t4(float4 v) {
    v.x = to_tf32(v.x); v.y = to_tf32(v.y);
    v.z = to_tf32(v.z); v.w = to_tf32(v.w);
    return v;
}
__device__ __forceinline__ void mma_tf32(float* c, const float4& a, const float2& b) {
    asm volatile(
        "mma.sync.aligned.m16n8k8.row.col.f32.tf32.tf32.f32 "
        "{%0,%1,%2,%3}, {%4,%5,%6,%7}, {%8,%9}, {%0,%1,%2,%3};"
        : "+f"(c[0]), "+f"(c[1]), "+f"(c[2]), "+f"(c[3])
        : "r"(__float_as_uint(a.x)), "r"(__float_as_uint(a.y)),
          "r"(__float_as_uint(a.z)), "r"(__float_as_uint(a.w)),
          "r"(__float_as_uint(b.x)), "r"(__float_as_uint(b.y)));
}
__device__ __forceinline__ void mma_bf16(float* c, const uint4& a, const uint2& b) {
    asm volatile(
        "mma.sync.aligned.m16n8k16.row.col.f32.bf16.bf16.f32 "
        "{%0,%1,%2,%3}, {%4,%5,%6,%7}, {%8,%9}, {%0,%1,%2,%3};"
        : "+f"(c[0]), "+f"(c[1]), "+f"(c[2]), "+f"(c[3])
        : "r"(a.x), "r"(a.y), "r"(a.z), "r"(a.w), "r"(b.x), "r"(b.y));
}
__device__ __forceinline__ void cp16(void* smem, const void* gmem) {
    unsigned s = (unsigned)__cvta_generic_to_shared(smem);
    asm volatile("cp.async.cg.shared.global [%0], [%1], 16;\n" :: "r"(s), "l"(gmem));
}

// ---------------- 1. gather + concat (padded, tf32-rounded) ------------------
__global__ void gather_kernel(const int* __restrict__ char_idx,
                              const int* __restrict__ ctype_idx,
                              const int* __restrict__ lbi_idx,
                              const int* __restrict__ rbi_idx,
                              const int* __restrict__ ext_idx,
                              const int* __restrict__ lext_idx,
                              const int* __restrict__ rext_idx,
                              const float* __restrict__ charEmb,
                              const float* __restrict__ ctypeEmb,
                              const float* __restrict__ biEmb,
                              const float* __restrict__ extEmb,
                              const float* __restrict__ extBiEmb)
{
    int t = blockIdx.x;
    int tid = threadIdx.x;             // 128 threads
    float* L = g_catL + (size_t)t * KPAD;
    float* R = g_catR + (size_t)t * KPAD;

    int ci = char_idx[t];
    int ct = ctype_idx[t];
    int lb = lbi_idx[t];
    int rb = rbi_idx[t];
    int ec = ext_idx[t];
    int le = lext_idx[t];
    int re = rext_idx[t];

    const float4* c4  = (const float4*)(charEmb  + (size_t)ci * 200);
    const float4* e4  = (const float4*)(extEmb   + (size_t)ec * 200);
    const float4* lb4 = (const float4*)(biEmb    + (size_t)lb * 200);
    const float4* rb4 = (const float4*)(biEmb    + (size_t)rb * 200);
    const float4* le4 = (const float4*)(extBiEmb + (size_t)le * 200);
    const float4* re4 = (const float4*)(extBiEmb + (size_t)re * 200);

    for (int i = tid; i < 50; i += 128) {
        float4 v = t4(c4[i]);
        ((float4*)L)[i] = v;           ((float4*)R)[i] = v;
        v = t4(e4[i]);
        ((float4*)(L + 200))[i] = v;   ((float4*)(R + 200))[i] = v;
        ((float4*)(L + 400))[i] = t4(lb4[i]);
        ((float4*)(R + 400))[i] = t4(rb4[i]);
        ((float4*)(L + 600))[i] = t4(le4[i]);
        ((float4*)(R + 600))[i] = t4(re4[i]);
    }
    const float* cty = ctypeEmb + (size_t)ct * 50;
    for (int i = tid; i < KPAD - 800; i += 128) {
        float v = (i < 50) ? to_tf32(cty[i]) : 0.f;
        L[800 + i] = v;
        R[800 + i] = v;
    }
}

// ---------------- 1b. weight prep (pad + tf32 round) -------------------------
__global__ void prep_w_kernel(const float* __restrict__ W_lin)
{
    int n = blockIdx.x;
    const float* src = W_lin + (size_t)n * KRAW;
    float* dst = g_Wpad + (size_t)n * KPAD;
    for (int i = threadIdx.x; i < KPAD; i += blockDim.x)
        dst[i] = (i < KRAW) ? to_tf32(src[i]) : 0.f;
}

__global__ void prep_wih_kernel(const float* __restrict__ Wl,
                                const float* __restrict__ Wr)
{
    int i = blockIdx.x * blockDim.x + threadIdx.x;
    int n = G4 * HID;
    for (int j = i; j < n; j += gridDim.x * blockDim.x) {
        g_WihL[j] = to_tf32(Wl[j]);
        g_WihR[j] = to_tf32(Wr[j]);
    }
}

// ---------------- 2. stage-1 tensor GEMM: tanh(cat @ W_lin^T + b) ------------
#define TS 4608   // floats per smem tile (128 x 36)

template <int SIDE>
__global__ __launch_bounds__(256, 2) void gemm1_tc(const float* __restrict__ bias)
{
    extern __shared__ float smx[];
    const float* A = SIDE ? g_catR : g_catL;
    float*       C = SIDE ? g_inR  : g_inL;
    const float* Bw = g_Wpad;

    int tid = threadIdx.x, l = tid & 31, w = tid >> 5;
    int wm = w & 1, wn = w >> 1;
    int m0 = blockIdx.y * 128, n0 = blockIdx.x * 128;

    float acc[4][4][4];
#pragma unroll
    for (int mi = 0; mi < 4; mi++)
#pragma unroll
        for (int nt = 0; nt < 4; nt++)
#pragma unroll
            for (int r = 0; r < 4; r++) acc[mi][nt][r] = 0.f;

    const int NS = KPAD / 32;   // 27

    {
        float* As = smx; float* Bs = smx + TS;
#pragma unroll
        for (int r = 0; r < 4; r++) {
            int id = tid + r * 256;
            int row = id >> 3, kg = (id & 7) << 2;
            cp16(&As[row * 36 + kg], &A[(size_t)(m0 + row) * KPAD + kg]);
            cp16(&Bs[row * 36 + kg], &Bw[(size_t)(n0 + row) * KPAD + kg]);
        }
        asm volatile("cp.async.commit_group;\n");
    }

    for (int ks = 0; ks < NS; ks++) {
        if (ks + 1 < NS) {
            int k0 = (ks + 1) * 32;
            float* As = smx + ((ks + 1) & 1) * 2 * TS;
            float* Bs = As + TS;
#pragma unroll
            for (int r = 0; r < 4; r++) {
                int id = tid + r * 256;
                int row = id >> 3, kg = (id & 7) << 2;
                cp16(&As[row * 36 + kg], &A[(size_t)(m0 + row) * KPAD + k0 + kg]);
                cp16(&Bs[row * 36 + kg], &Bw[(size_t)(n0 + row) * KPAD + k0 + kg]);
            }
            asm volatile("cp.async.commit_group;\n");
            asm volatile("cp.async.wait_group 1;\n");
        } else {
            asm volatile("cp.async.wait_group 0;\n");
        }
        __syncthreads();

        float* As = smx + (ks & 1) * 2 * TS;
        float* Bs = As + TS;
#pragma unroll
        for (int ki = 0; ki < 4; ki++) {
            int kk = ki * 8;
            float4 a[4]; float2 b[4];
#pragma unroll
            for (int mi = 0; mi < 4; mi++) {
                int r0 = wm * 64 + mi * 16 + (l >> 2);
                a[mi].x = As[r0 * 36 + kk + (l & 3)];
                a[mi].y = As[(r0 + 8) * 36 + kk + (l & 3)];
                a[mi].z = As[r0 * 36 + kk + (l & 3) + 4];
                a[mi].w = As[(r0 + 8) * 36 + kk + (l & 3) + 4];
            }
#pragma unroll
            for (int nt = 0; nt < 4; nt++) {
                int c0 = wn * 32 + nt * 8 + (l >> 2);
                b[nt].x = Bs[c0 * 36 + kk + (l & 3)];
                b[nt].y = Bs[c0 * 36 + kk + (l & 3) + 4];
            }
#pragma unroll
            for (int mi = 0; mi < 4; mi++)
#pragma unroll
                for (int nt = 0; nt < 4; nt++)
                    mma_tf32(acc[mi][nt], a[mi], b[nt]);
        }
        __syncthreads();
    }

#pragma unroll
    for (int mi = 0; mi < 4; mi++) {
#pragma unroll
        for (int rh = 0; rh < 2; rh++) {
            int row = m0 + wm * 64 + mi * 16 + (l >> 2) + rh * 8;
#pragma unroll
            for (int nt = 0; nt < 4; nt++) {
                int col = n0 + wn * 32 + nt * 8 + (l & 3) * 2;
                float2 bv = *(const float2*)&bias[col];
                float2 v;
                v.x = to_tf32(tanhf(acc[mi][nt][rh * 2 + 0] + bv.x));
                v.y = to_tf32(tanhf(acc[mi][nt][rh * 2 + 1] + bv.y));
                *(float2*)&C[(size_t)row * HID + col] = v;
            }
        }
    }
}

// ---------------- 3. stage-2 tensor GEMM: xg = in @ W_ih^T + biases ----------
template <int SIDE>
__global__ __launch_bounds__(256, 2) void gemm2_tc(const float* __restrict__ b_ih,
                                                   const float* __restrict__ b_hh)
{
    extern __shared__ float smx[];
    const float* A  = SIDE ? g_inR  : g_inL;
    const float* Bw = SIDE ? g_WihR : g_WihL;
    float*       C  = SIDE ? g_xgR  : g_xgL;

    int tid = threadIdx.x, l = tid & 31, w = tid >> 5;
    int wm = w & 1, wn = w >> 1;
    int m0 = blockIdx.y * 128, n0 = blockIdx.x * 128;

    float acc[4][4][4];
#pragma unroll
    for (int mi = 0; mi < 4; mi++)
#pragma unroll
        for (int nt = 0; nt < 4; nt++)
#pragma unroll
            for (int r = 0; r < 4; r++) acc[mi][nt][r] = 0.f;

    const int NS = HID / 32;   // 16

    {
        float* As = smx; float* Bs = smx + TS;
#pragma unroll
        for (int r = 0; r < 4; r++) {
            int id = tid + r * 256;
            int row = id >> 3, kg = (id & 7) << 2;
            cp16(&As[row * 36 + kg], &A[(size_t)(m0 + row) * HID + kg]);
            cp16(&Bs[row * 36 + kg], &Bw[(size_t)(n0 + row) * HID + kg]);
        }
        asm volatile("cp.async.commit_group;\n");
    }

    for (int ks = 0; ks < NS; ks++) {
        if (ks + 1 < NS) {
            int k0 = (ks + 1) * 32;
            float* As = smx + ((ks + 1) & 1) * 2 * TS;
            float* Bs = As + TS;
#pragma unroll
            for (int r = 0; r < 4; r++) {
                int id = tid + r * 256;
                int row = id >> 3, kg = (id & 7) << 2;
                cp16(&As[row * 36 + kg], &A[(size_t)(m0 + row) * HID + k0 + kg]);
                cp16(&Bs[row * 36 + kg], &Bw[(size_t)(n0 + row) * HID + k0 + kg]);
            }
            asm volatile("cp.async.commit_group;\n");
            asm volatile("cp.async.wait_group 1;\n");
        } else {
            asm volatile("cp.async.wait_group 0;\n");
        }
        __syncthreads();

        float* As = smx + (ks & 1) * 2 * TS;
        float* Bs = As + TS;
#pragma unroll
        for (int ki = 0; ki < 4; ki++) {
            int kk = ki * 8;
            float4 a[4]; float2 b[4];
#pragma unroll
            for (int mi = 0; mi < 4; mi++) {
                int r0 = wm * 64 + mi * 16 + (l >> 2);
                a[mi].x = As[r0 * 36 + kk + (l & 3)];
                a[mi].y = As[(r0 + 8) * 36 + kk + (l & 3)];
                a[mi].z = As[r0 * 36 + kk + (l & 3) + 4];
                a[mi].w = As[(r0 + 8) * 36 + kk + (l & 3) + 4];
            }
#pragma unroll
            for (int nt = 0; nt < 4; nt++) {
                int c0 = wn * 32 + nt * 8 + (l >> 2);
                b[nt].x = Bs[c0 * 36 + kk + (l & 3)];
                b[nt].y = Bs[c0 * 36 + kk + (l & 3) + 4];
            }
#pragma unroll
            for (int mi = 0; mi < 4; mi++)
#pragma unroll
                for (int nt = 0; nt < 4; nt++)
                    mma_tf32(acc[mi][nt], a[mi], b[nt]);
        }
        __syncthreads();
    }

#pragma unroll
    for (int mi = 0; mi < 4; mi++) {
#pragma unroll
        for (int rh = 0; rh < 2; rh++) {
            int m = m0 + wm * 64 + mi * 16 + (l >> 2) + rh * 8;
            int s = m & (SS - 1);
            int b = m >> 9;
            float* crow = C + ((size_t)s * BB + b) * G4;
#pragma unroll
            for (int nt = 0; nt < 4; nt++) {
                int col = n0 + wn * 32 + nt * 8 + (l & 3) * 2;
                float2 b1 = *(const float2*)&b_ih[col];
                float2 b2 = *(const float2*)&b_hh[col];
                float2 v;
                v.x = acc[mi][nt][rh * 2 + 0] + b1.x + b2.x;
                v.y = acc[mi][nt][rh * 2 + 1] + b1.y + b2.y;
                *(float2*)&crow[col] = v;
            }
        }
    }
}

// ---------------- 4. reset LSTM state ----------------------------------------
__global__ void init_kernel()
{
    int i = blockIdx.x * blockDim.x + threadIdx.x;
    if (i < 2) g_cnt[i] = 0u;
    unsigned* h = (unsigned*)&g_hbf[0][0][0];
    int n = 2 * 2 * BB * HID / 2;
    for (int j = i; j < n; j += gridDim.x * blockDim.x) h[j] = 0u;
}

// ---------------- 5. persistent bidirectional LSTM (bf16 tensor cores) -------
// 128 CTAs (PROVEN R7 structure): dir = bid>>6, CTA owns 8 hidden units
// (32 gate cols).  Warp = (mt 0..3) x (kq 0..1); kq=1 partials via Pb; kq=0
// does the cell update in registers (c-state in regs), tanh.approx gates.
// SMEM bytes: Wh bf16 32768 | Pb f32 8704 | Xs f32 2x8192
#define SMB_WH   0
#define SMB_PB   32768
#define SMB_XS   41472
#define SMB_TOT  57856

__global__ __launch_bounds__(256, 1) void lstm_kernel(const float* __restrict__ Whl,
                                                      const float* __restrict__ Whr,
                                                      float* __restrict__ out)
{
    extern __shared__ char smraw[];
    __nv_bfloat16* Wh = (__nv_bfloat16*)(smraw + SMB_WH);
    unsigned* Wh32    = (unsigned*)(smraw + SMB_WH);
    float* Pb  = (float*)(smraw + SMB_PB);
    float* Xs0 = (float*)(smraw + SMB_XS);
    float* Xs1 = (float*)(smraw + SMB_XS + 8192);

    int tid = threadIdx.x;
    int bid = blockIdx.x;
    int dir = bid >> 6;
    int n0  = (bid & 63) << 3;

    const float* Whh = dir ? Whr : Whl;
    const float* xg  = dir ? g_xgR : g_xgL;
    __nv_bfloat16* hb0 = g_hbf[dir][0];
    __nv_bfloat16* hb1 = g_hbf[dir][1];
    unsigned* cnt = &g_cnt[dir];

    // pack W slice into m16n8k16 B-fragment layout (bf16), once
    for (int id = tid; id < 16384; id += 256) {
        int half = id & 1;
        int e    = (id >> 1) & 1;
        int lane = (id >> 2) & 31;
        int nt   = (id >> 7) & 3;
        int ki   = id >> 9;
        int k    = ki * 16 + e * 8 + (lane & 3) * 2 + half;
        int c    = nt * 8 + (lane >> 2);
        int grow = ((c >> 3) << 9) + n0 + (c & 7);
        Wh[id] = __float2bfloat16_rn(Whh[(size_t)grow * 512 + k]);
    }

    int lane = tid & 31;
    int w    = tid >> 5;
    int mt   = w & 3;
    int kq   = w >> 2;                 // 0/1 : K halves

    float creg[4];                     // cell state (kq==0 threads)
#pragma unroll
    for (int r = 0; r < 4; r++) creg[r] = 0.f;

    // prefetch xg for step 0
    {
        int t0 = dir ? (SS - 1) : 0;
        size_t xb = (size_t)t0 * (BB * G4);
        for (int r = 0; r < 2; r++) {
            int id = tid + r * 256;
            int m = id >> 3, seg = (id >> 1) & 3, q = id & 1;
            cp16(&Xs0[(m * 4 + seg) * 8 + q * 4],
                 &xg[xb + (size_t)m * G4 + n0 + seg * 512 + q * 4]);
        }
        asm volatile("cp.async.commit_group;\n");
    }
    __syncthreads();

    int slot17 = (mt * 32 + lane) * 17;

    for (int it = 0; it < SS; it++) {
        int t = dir ? (SS - 1 - it) : it;
        const unsigned* hprev32 = (const unsigned*)((it & 1) ? hb1 : hb0);
        __nv_bfloat16*  hnext   = (it & 1) ? hb0 : hb1;
        float* Xc = (it & 1) ? Xs1 : Xs0;
        float* Xn = (it & 1) ? Xs0 : Xs1;

        // ---- bf16 mma: A-fragments straight from L2 -------------------------
        float acc[4][4];
#pragma unroll
        for (int nt = 0; nt < 4; nt++)
#pragma unroll
            for (int r = 0; r < 4; r++) acc[nt][r] = 0.f;

        const uint4* ap = (const uint4*)&hprev32[(((kq * 16) * 4 + mt) * 32 + lane) * 4];
#pragma unroll
        for (int kl = 0; kl < 16; kl++) {
            uint4 a = __ldcg(ap + kl * 128);       // ki stride: 4*32*4 u32 = 128 uint4
            int ki = kq * 16 + kl;
#pragma unroll
            for (int nt = 0; nt < 4; nt++) {
                uint2 b = *(const uint2*)&Wh32[((ki * 4 + nt) * 32 + lane) * 2];
                mma_bf16(acc[nt], a, b);
            }
        }

        // ---- K-partial exchange: kq=1 -> smem -------------------------------
        if (kq) {
#pragma unroll
            for (int nt = 0; nt < 4; nt++)
#pragma unroll
                for (int r = 0; r < 4; r++)
                    Pb[slot17 + nt * 4 + r] = acc[nt][r];
        }
        asm volatile("cp.async.wait_group 0;\n");
        __syncthreads();

        if (!kq) {
            // ---- full cell update in registers (tanh.approx gates) ----------
#pragma unroll
            for (int rh = 0; rh < 2; rh++) {
                int m = mt * 16 + (lane >> 2) + rh * 8;
                const float* xr = &Xc[m * 32];
                int je = (lane & 3) * 2;           // even unit of the pair
                float hpair[2];
#pragma unroll
                for (int c = 0; c < 2; c++) {
                    int r = rh * 2 + c;
                    int j = je + c;
                    float gi = acc[0][r] + Pb[slot17 + 0 + r]  + xr[j];
                    float gf = acc[1][r] + Pb[slot17 + 4 + r]  + xr[8 + j];
                    float gg = acc[2][r] + Pb[slot17 + 8 + r]  + xr[16 + j];
                    float go = acc[3][r] + Pb[slot17 + 12 + r] + xr[24 + j];
                    float cn = siga(gf) * creg[r] + siga(gi) * tanha(gg);
                    float h  = siga(go) * tanha(cn);
                    creg[r] = cn;
                    hpair[c] = h;
                }
                // packed bf16x2 h write (both halves of one word)
                int kge = n0 + je;
                int ki2 = kge >> 4;
                int ln  = (m & 7) * 4 + ((kge >> 1) & 3);
                int e   = ((m >> 3) & 1) + 2 * ((kge >> 3) & 1);
                unsigned word = (__bfloat16_as_ushort(__float2bfloat16_rn(hpair[0]))) |
                                ((unsigned)__bfloat16_as_ushort(__float2bfloat16_rn(hpair[1])) << 16);
                unsigned* dst = (unsigned*)hnext + ((ki2 * 4 + mt) * 32 + ln) * 4 + e;
                asm volatile("st.global.cg.u32 [%0], %1;" :: "l"(dst), "r"(word));
                // fp32 output write
                float2 ov; ov.x = hpair[0]; ov.y = hpair[1];
                *(float2*)&out[((size_t)m * SS + t) * 1024 + (dir << 9) + n0 + je] = ov;
            }
        }

        // ---- prefetch next step's xg (overlaps barrier wait) ----------------
        if (it + 1 < SS) {
            int tn = dir ? (SS - 2 - it) : (it + 1);
            size_t xb = (size_t)tn * (BB * G4);
            for (int r = 0; r < 2; r++) {
                int id = tid + r * 256;
                int m = id >> 3, seg = (id >> 1) & 3, q = id & 1;
                cp16(&Xn[(m * 4 + seg) * 8 + q * 4],
                     &xg[xb + (size_t)m * G4 + n0 + seg * 512 + q * 4]);
            }
            asm volatile("cp.async.commit_group;\n");

            // ---- single-counter grid barrier (per direction) ----------------
            __syncthreads();
            if (tid == 0) {
                __threadfence();
                atomicAdd(cnt, 1u);
                unsigned tgt = 64u * (unsigned)(it + 1);
                unsigned v;
                while (true) {
                    asm volatile("ld.global.cg.u32 %0, [%1];" : "=r"(v) : "l"(cnt));
                    if (v >= tgt) break;
                    __nanosleep(16);
                }
            }
            __syncthreads();
        }
    }
}

// ---------------- host launch -------------------------------------------------
extern "C" void kernel_launch(void* const* d_in, const int* in_sizes, int n_in,
                              void* d_out, int out_size)
{
    const int*   char_idx  = (const int*)d_in[0];
    const int*   ctype_idx = (const int*)d_in[1];
    const int*   lbi_idx   = (const int*)d_in[2];
    const int*   rbi_idx   = (const int*)d_in[3];
    const int*   ext_idx   = (const int*)d_in[4];
    const int*   lext_idx  = (const int*)d_in[5];
    const int*   rext_idx  = (const int*)d_in[6];
    const float* charEmb   = (const float*)d_in[7];
    const float* ctypeEmb  = (const float*)d_in[8];
    const float* biEmb     = (const float*)d_in[9];
    const float* extEmb    = (const float*)d_in[10];
    const float* extBiEmb  = (const float*)d_in[11];
    const float* W_lin     = (const float*)d_in[12];
    const float* b_lin     = (const float*)d_in[13];
    const float* W_ih_l    = (const float*)d_in[14];
    const float* W_hh_l    = (const float*)d_in[15];
    const float* b_ih_l    = (const float*)d_in[16];
    const float* b_hh_l    = (const float*)d_in[17];
    const float* W_ih_r    = (const float*)d_in[18];
    const float* W_hh_r    = (const float*)d_in[19];
    const float* b_ih_r    = (const float*)d_in[20];
    const float* b_hh_r    = (const float*)d_in[21];
    float* out = (float*)d_out;

    gather_kernel<<<MTOT, 128>>>(char_idx, ctype_idx, lbi_idx, rbi_idx,
                                 ext_idx, lext_idx, rext_idx,
                                 charEmb, ctypeEmb, biEmb, extEmb, extBiEmb);
    prep_w_kernel<<<512, 128>>>(W_lin);
    prep_wih_kernel<<<256, 256>>>(W_ih_l, W_ih_r);

    const int gsm = 4 * TS * 4;   // 73728 B
    cudaFuncSetAttribute(gemm1_tc<0>, cudaFuncAttributeMaxDynamicSharedMemorySize, gsm);
    cudaFuncSetAttribute(gemm1_tc<1>, cudaFuncAttributeMaxDynamicSharedMemorySize, gsm);
    cudaFuncSetAttribute(gemm2_tc<0>, cudaFuncAttributeMaxDynamicSharedMemorySize, gsm);
    cudaFuncSetAttribute(gemm2_tc<1>, cudaFuncAttributeMaxDynamicSharedMemorySize, gsm);

    gemm1_tc<0><<<dim3(4, 256), 256, gsm>>>(b_lin);
    gemm1_tc<1><<<dim3(4, 256), 256, gsm>>>(b_lin);
    gemm2_tc<0><<<dim3(16, 256), 256, gsm>>>(b_ih_l, b_hh_l);
    gemm2_tc<1><<<dim3(16, 256), 256, gsm>>>(b_ih_r, b_hh_r);

    init_kernel<<<64, 256>>>();

    cudaFuncSetAttribute(lstm_kernel, cudaFuncAttributeMaxDynamicSharedMemorySize,
                         SMB_TOT);
    lstm_kernel<<<128, 256, SMB_TOT>>>(W_hh_l, W_hh_r, out);
}

// round 14
// speedup vs baseline: 1.4593x; 1.4593x over previous
#include <cuda_runtime.h>
#include <cuda_bf16.h>

#define BB   64
#define SS   512
#define KRAW 850
#define KPAD 864
#define HID  512
#define G4   2048
#define MTOT (BB * SS)

// ---------------- scratch (static device globals; no runtime alloc) ----------
__device__ __align__(16) float g_Wpad[(size_t)HID * KPAD];
__device__ __align__(16) float g_ct64[8 * 64];             // padded tf32 ctype table
__device__ __align__(16) float g_WihL[(size_t)G4 * HID];
__device__ __align__(16) float g_WihR[(size_t)G4 * HID];
__device__ __align__(16) float g_inL[(size_t)MTOT * HID];
__device__ __align__(16) float g_inR[(size_t)MTOT * HID];
__device__ __align__(16) float g_xgL[(size_t)MTOT * G4];   // [S][B][2048]
__device__ __align__(16) float g_xgR[(size_t)MTOT * G4];
// h double buffer, bf16, m16n8k16 A-fragment packed (see lstm_kernel)
__device__ __align__(16) __nv_bfloat16 g_hbf[2][2][BB * HID];
__device__ unsigned g_cnt[2];                  // per-direction step counter

__device__ __forceinline__ float tanha(float x) {
    float r;
    asm("tanh.approx.f32 %0, %1;" : "=f"(r) : "f"(x));
    return r;
}
__device__ __forceinline__ float siga(float x) {
    return fmaf(0.5f, tanha(0.5f * x), 0.5f);
}
__device__ __forceinline__ float to_tf32(float x) {
    float r;
    asm("cvt.rna.tf32.f32 %0, %1;" : "=f"(r) : "f"(x));
    return r;
}
__device__ __forceinline__ void mma_tf32(float* c, const float4& a, const float2& b) {
    asm volatile(
        "mma.sync.aligned.m16n8k8.row.col.f32.tf32.tf32.f32 "
        "{%0,%1,%2,%3}, {%4,%5,%6,%7}, {%8,%9}, {%0,%1,%2,%3};"
        : "+f"(c[0]), "+f"(c[1]), "+f"(c[2]), "+f"(c[3])
        : "r"(__float_as_uint(a.x)), "r"(__float_as_uint(a.y)),
          "r"(__float_as_uint(a.z)), "r"(__float_as_uint(a.w)),
          "r"(__float_as_uint(b.x)), "r"(__float_as_uint(b.y)));
}
__device__ __forceinline__ void mma_bf16(float* c, const uint4& a, const uint2& b) {
    asm volatile(
        "mma.sync.aligned.m16n8k16.row.col.f32.bf16.bf16.f32 "
        "{%0,%1,%2,%3}, {%4,%5,%6,%7}, {%8,%9}, {%0,%1,%2,%3};"
        : "+f"(c[0]), "+f"(c[1]), "+f"(c[2]), "+f"(c[3])
        : "r"(a.x), "r"(a.y), "r"(a.z), "r"(a.w), "r"(b.x), "r"(b.y));
}
__device__ __forceinline__ void cp16(void* smem, const void* gmem) {
    unsigned s = (unsigned)__cvta_generic_to_shared(smem);
    asm volatile("cp.async.cg.shared.global [%0], [%1], 16;\n" :: "r"(s), "l"(gmem));
}

// ---------------- 1. weight prep (pad + tf32 round; + ctype pad table) -------
__global__ void prep_w_kernel(const float* __restrict__ W_lin)
{
    int n = blockIdx.x;
    const float* src = W_lin + (size_t)n * KRAW;
    float* dst = g_Wpad + (size_t)n * KPAD;
    for (int i = threadIdx.x; i < KPAD; i += blockDim.x)
        dst[i] = (i < KRAW) ? to_tf32(src[i]) : 0.f;
}

__global__ void prep_wih_kernel(const float* __restrict__ Wl,
                                const float* __restrict__ Wr,
                                const float* __restrict__ ctypeEmb)
{
    if (blockIdx.x == 0 && threadIdx.x < 512) {
        int ty = threadIdx.x >> 6, c = threadIdx.x & 63;
        g_ct64[threadIdx.x] = (c < 50) ? to_tf32(ctypeEmb[ty * 50 + c]) : 0.f;
    }
    int i = blockIdx.x * blockDim.x + threadIdx.x;
    int n = G4 * HID;
    for (int j = i; j < n; j += gridDim.x * blockDim.x) {
        g_WihL[j] = to_tf32(Wl[j]);
        g_WihR[j] = to_tf32(Wr[j]);
    }
}

// ---------------- 2. stage-1 tensor GEMM with FUSED embedding gather ---------
// C[32768,512] = tanh(concat(emb rows) @ W_lin^T + b).  A-tiles are assembled
// on the fly: cp.async 16B chunks sourced straight from the embedding tables.
#define TS 4608   // floats per smem tile (128 x 36)
#define IDX_OFF (4 * TS)   // int region: [0:128) char, [128) ext, [256) bi,
                           // [384) xbi, [512) ctype
#define GSM_BYTES ((4 * TS + 640) * 4)

template <int SIDE>
__global__ __launch_bounds__(256, 2) void gemm1_tc(
    const int* __restrict__ char_idx, const int* __restrict__ ext_idx,
    const int* __restrict__ lbi,      const int* __restrict__ rbi,
    const int* __restrict__ lext,     const int* __restrict__ rext,
    const int* __restrict__ ctype_idx,
    const float* __restrict__ charEmb, const float* __restrict__ extEmb,
    const float* __restrict__ biEmb,   const float* __restrict__ xbiEmb,
    const float* __restrict__ bias)
{
    extern __shared__ float smx[];
    int* si = (int*)(smx + IDX_OFF);
    float* C = SIDE ? g_inR : g_inL;
    const float* Bw = g_Wpad;

    int tid = threadIdx.x, l = tid & 31, w = tid >> 5;
    int wm = w & 1, wn = w >> 1;
    int m0 = blockIdx.y * 128, n0 = blockIdx.x * 128;

    // stage token indices for this CTA's 128 rows
    if (tid < 128) {
        int t = m0 + tid;
        si[tid]       = char_idx[t];
        si[128 + tid] = ext_idx[t];
        si[256 + tid] = SIDE ? rbi[t]  : lbi[t];
        si[384 + tid] = SIDE ? rext[t] : lext[t];
        si[512 + tid] = ctype_idx[t];
    }
    __syncthreads();

    float acc[4][4][4];
#pragma unroll
    for (int mi = 0; mi < 4; mi++)
#pragma unroll
        for (int nt = 0; nt < 4; nt++)
#pragma unroll
            for (int r = 0; r < 4; r++) acc[mi][nt][r] = 0.f;

    const int NS = KPAD / 32;   // 27

    // A-chunk loader: 16B chunk (row, kg) at global feature k0+kg
    auto ld_a = [&](float* As, int row, int kg, int k0) {
        int k = k0 + kg;
        const float* src;
        if (k < 200)      src = charEmb + (size_t)si[row] * 200 + k;
        else if (k < 400) src = extEmb  + (size_t)si[128 + row] * 200 + (k - 200);
        else if (k < 600) src = biEmb   + (size_t)si[256 + row] * 200 + (k - 400);
        else if (k < 800) src = xbiEmb  + (size_t)si[384 + row] * 200 + (k - 600);
        else              src = g_ct64 + si[512 + row] * 64 + (k - 800);
        cp16(&As[row * 36 + kg], src);
    };

    {   // preload stage 0
        float* As = smx; float* Bs = smx + TS;
#pragma unroll
        for (int r = 0; r < 4; r++) {
            int id = tid + r * 256;
            int row = id >> 3, kg = (id & 7) << 2;
            ld_a(As, row, kg, 0);
            cp16(&Bs[row * 36 + kg], &Bw[(size_t)(n0 + row) * KPAD + kg]);
        }
        asm volatile("cp.async.commit_group;\n");
    }

    for (int ks = 0; ks < NS; ks++) {
        if (ks + 1 < NS) {
            int k0 = (ks + 1) * 32;
            float* As = smx + ((ks + 1) & 1) * 2 * TS;
            float* Bs = As + TS;
#pragma unroll
            for (int r = 0; r < 4; r++) {
                int id = tid + r * 256;
                int row = id >> 3, kg = (id & 7) << 2;
                ld_a(As, row, kg, k0);
                cp16(&Bs[row * 36 + kg], &Bw[(size_t)(n0 + row) * KPAD + k0 + kg]);
            }
            asm volatile("cp.async.commit_group;\n");
            asm volatile("cp.async.wait_group 1;\n");
        } else {
            asm volatile("cp.async.wait_group 0;\n");
        }
        __syncthreads();

        float* As = smx + (ks & 1) * 2 * TS;
        float* Bs = As + TS;
#pragma unroll
        for (int ki = 0; ki < 4; ki++) {
            int kk = ki * 8;
            float4 a[4]; float2 b[4];
#pragma unroll
            for (int mi = 0; mi < 4; mi++) {
                int r0 = wm * 64 + mi * 16 + (l >> 2);
                a[mi].x = As[r0 * 36 + kk + (l & 3)];
                a[mi].y = As[(r0 + 8) * 36 + kk + (l & 3)];
                a[mi].z = As[r0 * 36 + kk + (l & 3) + 4];
                a[mi].w = As[(r0 + 8) * 36 + kk + (l & 3) + 4];
            }
#pragma unroll
            for (int nt = 0; nt < 4; nt++) {
                int c0 = wn * 32 + nt * 8 + (l >> 2);
                b[nt].x = Bs[c0 * 36 + kk + (l & 3)];
                b[nt].y = Bs[c0 * 36 + kk + (l & 3) + 4];
            }
#pragma unroll
            for (int mi = 0; mi < 4; mi++)
#pragma unroll
                for (int nt = 0; nt < 4; nt++)
                    mma_tf32(acc[mi][nt], a[mi], b[nt]);
        }
        __syncthreads();
    }

#pragma unroll
    for (int mi = 0; mi < 4; mi++) {
#pragma unroll
        for (int rh = 0; rh < 2; rh++) {
            int row = m0 + wm * 64 + mi * 16 + (l >> 2) + rh * 8;
#pragma unroll
            for (int nt = 0; nt < 4; nt++) {
                int col = n0 + wn * 32 + nt * 8 + (l & 3) * 2;
                float2 bv = *(const float2*)&bias[col];
                float2 v;
                v.x = to_tf32(tanhf(acc[mi][nt][rh * 2 + 0] + bv.x));
                v.y = to_tf32(tanhf(acc[mi][nt][rh * 2 + 1] + bv.y));
                *(float2*)&C[(size_t)row * HID + col] = v;
            }
        }
    }
}

// ---------------- 3. stage-2 tensor GEMM: xg = in @ W_ih^T + biases ----------
template <int SIDE>
__global__ __launch_bounds__(256, 2) void gemm2_tc(const float* __restrict__ b_ih,
                                                   const float* __restrict__ b_hh)
{
    extern __shared__ float smx[];
    const float* A  = SIDE ? g_inR  : g_inL;
    const float* Bw = SIDE ? g_WihR : g_WihL;
    float*       C  = SIDE ? g_xgR  : g_xgL;

    int tid = threadIdx.x, l = tid & 31, w = tid >> 5;
    int wm = w & 1, wn = w >> 1;
    int m0 = blockIdx.y * 128, n0 = blockIdx.x * 128;

    float acc[4][4][4];
#pragma unroll
    for (int mi = 0; mi < 4; mi++)
#pragma unroll
        for (int nt = 0; nt < 4; nt++)
#pragma unroll
            for (int r = 0; r < 4; r++) acc[mi][nt][r] = 0.f;

    const int NS = HID / 32;   // 16

    {
        float* As = smx; float* Bs = smx + TS;
#pragma unroll
        for (int r = 0; r < 4; r++) {
            int id = tid + r * 256;
            int row = id >> 3, kg = (id & 7) << 2;
            cp16(&As[row * 36 + kg], &A[(size_t)(m0 + row) * HID + kg]);
            cp16(&Bs[row * 36 + kg], &Bw[(size_t)(n0 + row) * HID + kg]);
        }
        asm volatile("cp.async.commit_group;\n");
    }

    for (int ks = 0; ks < NS; ks++) {
        if (ks + 1 < NS) {
            int k0 = (ks + 1) * 32;
            float* As = smx + ((ks + 1) & 1) * 2 * TS;
            float* Bs = As + TS;
#pragma unroll
            for (int r = 0; r < 4; r++) {
                int id = tid + r * 256;
                int row = id >> 3, kg = (id & 7) << 2;
                cp16(&As[row * 36 + kg], &A[(size_t)(m0 + row) * HID + k0 + kg]);
                cp16(&Bs[row * 36 + kg], &Bw[(size_t)(n0 + row) * HID + k0 + kg]);
            }
            asm volatile("cp.async.commit_group;\n");
            asm volatile("cp.async.wait_group 1;\n");
        } else {
            asm volatile("cp.async.wait_group 0;\n");
        }
        __syncthreads();

        float* As = smx + (ks & 1) * 2 * TS;
        float* Bs = As + TS;
#pragma unroll
        for (int ki = 0; ki < 4; ki++) {
            int kk = ki * 8;
            float4 a[4]; float2 b[4];
#pragma unroll
            for (int mi = 0; mi < 4; mi++) {
                int r0 = wm * 64 + mi * 16 + (l >> 2);
                a[mi].x = As[r0 * 36 + kk + (l & 3)];
                a[mi].y = As[(r0 + 8) * 36 + kk + (l & 3)];
                a[mi].z = As[r0 * 36 + kk + (l & 3) + 4];
                a[mi].w = As[(r0 + 8) * 36 + kk + (l & 3) + 4];
            }
#pragma unroll
            for (int nt = 0; nt < 4; nt++) {
                int c0 = wn * 32 + nt * 8 + (l >> 2);
                b[nt].x = Bs[c0 * 36 + kk + (l & 3)];
                b[nt].y = Bs[c0 * 36 + kk + (l & 3) + 4];
            }
#pragma unroll
            for (int mi = 0; mi < 4; mi++)
#pragma unroll
                for (int nt = 0; nt < 4; nt++)
                    mma_tf32(acc[mi][nt], a[mi], b[nt]);
        }
        __syncthreads();
    }

#pragma unroll
    for (int mi = 0; mi < 4; mi++) {
#pragma unroll
        for (int rh = 0; rh < 2; rh++) {
            int m = m0 + wm * 64 + mi * 16 + (l >> 2) + rh * 8;
            int s = m & (SS - 1);
            int b = m >> 9;
            float* crow = C + ((size_t)s * BB + b) * G4;
#pragma unroll
            for (int nt = 0; nt < 4; nt++) {
                int col = n0 + wn * 32 + nt * 8 + (l & 3) * 2;
                float2 b1 = *(const float2*)&b_ih[col];
                float2 b2 = *(const float2*)&b_hh[col];
                float2 v;
                v.x = acc[mi][nt][rh * 2 + 0] + b1.x + b2.x;
                v.y = acc[mi][nt][rh * 2 + 1] + b1.y + b2.y;
                *(float2*)&crow[col] = v;
            }
        }
    }
}

// ---------------- 4. reset LSTM state ----------------------------------------
__global__ void init_kernel()
{
    int i = blockIdx.x * blockDim.x + threadIdx.x;
    if (i < 2) g_cnt[i] = 0u;
    unsigned* h = (unsigned*)&g_hbf[0][0][0];
    int n = 2 * 2 * BB * HID / 2;
    for (int j = i; j < n; j += gridDim.x * blockDim.x) h[j] = 0u;
}

// ---------------- 5. persistent bidirectional LSTM (bf16 tensor cores) -------
// 128 CTAs (PROVEN structure): dir = bid>>6, CTA owns 8 hidden units
// (32 gate cols).  Warp = (mt 0..3) x (kq 0..1); kq=1 partials via Pb; kq=0
// does the cell update in registers (c-state in regs), tanh.approx gates.
// SMEM bytes: Wh bf16 32768 | Pb f32 8704 | Xs f32 2x8192
#define SMB_WH   0
#define SMB_PB   32768
#define SMB_XS   41472
#define SMB_TOT  57856

__global__ __launch_bounds__(256, 1) void lstm_kernel(const float* __restrict__ Whl,
                                                      const float* __restrict__ Whr,
                                                      float* __restrict__ out)
{
    extern __shared__ char smraw[];
    __nv_bfloat16* Wh = (__nv_bfloat16*)(smraw + SMB_WH);
    unsigned* Wh32    = (unsigned*)(smraw + SMB_WH);
    float* Pb  = (float*)(smraw + SMB_PB);
    float* Xs0 = (float*)(smraw + SMB_XS);
    float* Xs1 = (float*)(smraw + SMB_XS + 8192);

    int tid = threadIdx.x;
    int bid = blockIdx.x;
    int dir = bid >> 6;
    int n0  = (bid & 63) << 3;

    const float* Whh = dir ? Whr : Whl;
    const float* xg  = dir ? g_xgR : g_xgL;
    __nv_bfloat16* hb0 = g_hbf[dir][0];
    __nv_bfloat16* hb1 = g_hbf[dir][1];
    unsigned* cnt = &g_cnt[dir];

    // pack W slice into m16n8k16 B-fragment layout (bf16), once
    for (int id = tid; id < 16384; id += 256) {
        int half = id & 1;
        int e    = (id >> 1) & 1;
        int lane = (id >> 2) & 31;
        int nt   = (id >> 7) & 3;
        int ki   = id >> 9;
        int k    = ki * 16 + e * 8 + (lane & 3) * 2 + half;
        int c    = nt * 8 + (lane >> 2);
        int grow = ((c >> 3) << 9) + n0 + (c & 7);
        Wh[id] = __float2bfloat16_rn(Whh[(size_t)grow * 512 + k]);
    }

    int lane = tid & 31;
    int w    = tid >> 5;
    int mt   = w & 3;
    int kq   = w >> 2;                 // 0/1 : K halves

    float creg[4];                     // cell state (kq==0 threads)
#pragma unroll
    for (int r = 0; r < 4; r++) creg[r] = 0.f;

    // prefetch xg for step 0
    {
        int t0 = dir ? (SS - 1) : 0;
        size_t xb = (size_t)t0 * (BB * G4);
        for (int r = 0; r < 2; r++) {
            int id = tid + r * 256;
            int m = id >> 3, seg = (id >> 1) & 3, q = id & 1;
            cp16(&Xs0[(m * 4 + seg) * 8 + q * 4],
                 &xg[xb + (size_t)m * G4 + n0 + seg * 512 + q * 4]);
        }
        asm volatile("cp.async.commit_group;\n");
    }
    __syncthreads();

    int slot17 = (mt * 32 + lane) * 17;

    for (int it = 0; it < SS; it++) {
        int t = dir ? (SS - 1 - it) : it;
        const unsigned* hprev32 = (const unsigned*)((it & 1) ? hb1 : hb0);
        __nv_bfloat16*  hnext   = (it & 1) ? hb0 : hb1;
        float* Xc = (it & 1) ? Xs1 : Xs0;
        float* Xn = (it & 1) ? Xs0 : Xs1;

        // ---- bf16 mma: A-fragments straight from L2 -------------------------
        float acc[4][4];
#pragma unroll
        for (int nt = 0; nt < 4; nt++)
#pragma unroll
            for (int r = 0; r < 4; r++) acc[nt][r] = 0.f;

        const uint4* ap = (const uint4*)&hprev32[(((kq * 16) * 4 + mt) * 32 + lane) * 4];
#pragma unroll
        for (int kl = 0; kl < 16; kl++) {
            uint4 a = __ldcg(ap + kl * 128);       // ki stride: 4*32*4 u32 = 128 uint4
            int ki = kq * 16 + kl;
#pragma unroll
            for (int nt = 0; nt < 4; nt++) {
                uint2 b = *(const uint2*)&Wh32[((ki * 4 + nt) * 32 + lane) * 2];
                mma_bf16(acc[nt], a, b);
            }
        }

        // ---- K-partial exchange: kq=1 -> smem -------------------------------
        if (kq) {
#pragma unroll
            for (int nt = 0; nt < 4; nt++)
#pragma unroll
                for (int r = 0; r < 4; r++)
                    Pb[slot17 + nt * 4 + r] = acc[nt][r];
        }
        asm volatile("cp.async.wait_group 0;\n");
        __syncthreads();

        if (!kq) {
            // ---- full cell update in registers (tanh.approx gates) ----------
#pragma unroll
            for (int rh = 0; rh < 2; rh++) {
                int m = mt * 16 + (lane >> 2) + rh * 8;
                const float* xr = &Xc[m * 32];
                int je = (lane & 3) * 2;           // even unit of the pair
                float hpair[2];
#pragma unroll
                for (int c = 0; c < 2; c++) {
                    int r = rh * 2 + c;
                    int j = je + c;
                    float gi = acc[0][r] + Pb[slot17 + 0 + r]  + xr[j];
                    float gf = acc[1][r] + Pb[slot17 + 4 + r]  + xr[8 + j];
                    float gg = acc[2][r] + Pb[slot17 + 8 + r]  + xr[16 + j];
                    float go = acc[3][r] + Pb[slot17 + 12 + r] + xr[24 + j];
                    float cn = siga(gf) * creg[r] + siga(gi) * tanha(gg);
                    float h  = siga(go) * tanha(cn);
                    creg[r] = cn;
                    hpair[c] = h;
                }
                // packed bf16x2 h write (both halves of one word)
                int kge = n0 + je;
                int ki2 = kge >> 4;
                int ln  = (m & 7) * 4 + ((kge >> 1) & 3);
                int e   = ((m >> 3) & 1) + 2 * ((kge >> 3) & 1);
                unsigned word = (__bfloat16_as_ushort(__float2bfloat16_rn(hpair[0]))) |
                                ((unsigned)__bfloat16_as_ushort(__float2bfloat16_rn(hpair[1])) << 16);
                unsigned* dst = (unsigned*)hnext + ((ki2 * 4 + mt) * 32 + ln) * 4 + e;
                asm volatile("st.global.cg.u32 [%0], %1;" :: "l"(dst), "r"(word));
                // fp32 output write
                float2 ov; ov.x = hpair[0]; ov.y = hpair[1];
                *(float2*)&out[((size_t)m * SS + t) * 1024 + (dir << 9) + n0 + je] = ov;
            }
        }

        // ---- prefetch next step's xg (overlaps barrier wait) ----------------
        if (it + 1 < SS) {
            int tn = dir ? (SS - 2 - it) : (it + 1);
            size_t xb = (size_t)tn * (BB * G4);
            for (int r = 0; r < 2; r++) {
                int id = tid + r * 256;
                int m = id >> 3, seg = (id >> 1) & 3, q = id & 1;
                cp16(&Xn[(m * 4 + seg) * 8 + q * 4],
                     &xg[xb + (size_t)m * G4 + n0 + seg * 512 + q * 4]);
            }
            asm volatile("cp.async.commit_group;\n");

            // ---- single-counter grid barrier (per direction) ----------------
            __syncthreads();
            if (tid == 0) {
                __threadfence();
                atomicAdd(cnt, 1u);
                unsigned tgt = 64u * (unsigned)(it + 1);
                unsigned v;
                while (true) {
                    asm volatile("ld.global.cg.u32 %0, [%1];" : "=r"(v) : "l"(cnt));
                    if (v >= tgt) break;
                    __nanosleep(16);
                }
            }
            __syncthreads();
        }
    }
}

// ---------------- host launch -------------------------------------------------
extern "C" void kernel_launch(void* const* d_in, const int* in_sizes, int n_in,
                              void* d_out, int out_size)
{
    const int*   char_idx  = (const int*)d_in[0];
    const int*   ctype_idx = (const int*)d_in[1];
    const int*   lbi_idx   = (const int*)d_in[2];
    const int*   rbi_idx   = (const int*)d_in[3];
    const int*   ext_idx   = (const int*)d_in[4];
    const int*   lext_idx  = (const int*)d_in[5];
    const int*   rext_idx  = (const int*)d_in[6];
    const float* charEmb   = (const float*)d_in[7];
    const float* ctypeEmb  = (const float*)d_in[8];
    const float* biEmb     = (const float*)d_in[9];
    const float* extEmb    = (const float*)d_in[10];
    const float* extBiEmb  = (const float*)d_in[11];
    const float* W_lin     = (const float*)d_in[12];
    const float* b_lin     = (const float*)d_in[13];
    const float* W_ih_l    = (const float*)d_in[14];
    const float* W_hh_l    = (const float*)d_in[15];
    const float* b_ih_l    = (const float*)d_in[16];
    const float* b_hh_l    = (const float*)d_in[17];
    const float* W_ih_r    = (const float*)d_in[18];
    const float* W_hh_r    = (const float*)d_in[19];
    const float* b_ih_r    = (const float*)d_in[20];
    const float* b_hh_r    = (const float*)d_in[21];
    float* out = (float*)d_out;

    prep_w_kernel<<<512, 128>>>(W_lin);
    prep_wih_kernel<<<256, 512>>>(W_ih_l, W_ih_r, ctypeEmb);

    cudaFuncSetAttribute(gemm1_tc<0>, cudaFuncAttributeMaxDynamicSharedMemorySize, GSM_BYTES);
    cudaFuncSetAttribute(gemm1_tc<1>, cudaFuncAttributeMaxDynamicSharedMemorySize, GSM_BYTES);
    cudaFuncSetAttribute(gemm2_tc<0>, cudaFuncAttributeMaxDynamicSharedMemorySize, GSM_BYTES);
    cudaFuncSetAttribute(gemm2_tc<1>, cudaFuncAttributeMaxDynamicSharedMemorySize, GSM_BYTES);

    gemm1_tc<0><<<dim3(4, 256), 256, GSM_BYTES>>>(
        char_idx, ext_idx, lbi_idx, rbi_idx, lext_idx, rext_idx, ctype_idx,
        charEmb, extEmb, biEmb, extBiEmb, b_lin);
    gemm1_tc<1><<<dim3(4, 256), 256, GSM_BYTES>>>(
        char_idx, ext_idx, lbi_idx, rbi_idx, lext_idx, rext_idx, ctype_idx,
        charEmb, extEmb, biEmb, extBiEmb, b_lin);
    gemm2_tc<0><<<dim3(16, 256), 256, GSM_BYTES>>>(b_ih_l, b_hh_l);
    gemm2_tc<1><<<dim3(16, 256), 256, GSM_BYTES>>>(b_ih_r, b_hh_r);

    init_kernel<<<64, 256>>>();

    cudaFuncSetAttribute(lstm_kernel, cudaFuncAttributeMaxDynamicSharedMemorySize,
                         SMB_TOT);
    lstm_kernel<<<128, 256, SMB_TOT>>>(W_hh_l, W_hh_r, out);
}

// round 15
// speedup vs baseline: 1.5684x; 1.0747x over previous
#include <cuda_runtime.h>
#include <cuda_bf16.h>

#define BB   64
#define SS   512
#define KRAW 850
#define KPAD 864
#define HID  512
#define G4   2048
#define MTOT (BB * SS)

// ---------------- scratch (static device globals; no runtime alloc) ----------
// W_lin in tf32 B-fragment layout: [nblk 64][ki 108][lane 32][e 2]
__device__ __align__(16) float g_WpadF[64 * 108 * 64];
__device__ __align__(16) float g_ct64[8 * 64];             // padded tf32 ctype table
// W_ih in tf32 B-fragment layout: [nblk 256][ki 64][lane 32][e 2]
__device__ __align__(16) float g_WihF[2][(size_t)256 * 64 * 64];
// 'in' in tf32 A-fragment layout: [mblk 2048][ki 64][lane 32][e 4]
__device__ __align__(16) float g_inF[2][(size_t)2048 * 64 * 128];
__device__ __align__(16) float g_xgL[(size_t)MTOT * G4];   // [S][B][2048]
__device__ __align__(16) float g_xgR[(size_t)MTOT * G4];
// h double buffer, bf16, m16n8k16 A-fragment packed (see lstm_kernel)
__device__ __align__(16) __nv_bfloat16 g_hbf[2][2][BB * HID];
__device__ unsigned g_cnt[2];                  // per-direction step counter

__device__ __forceinline__ float tanha(float x) {
    float r;
    asm("tanh.approx.f32 %0, %1;" : "=f"(r) : "f"(x));
    return r;
}
__device__ __forceinline__ float siga(float x) {
    return fmaf(0.5f, tanha(0.5f * x), 0.5f);
}
__device__ __forceinline__ float to_tf32(float x) {
    float r;
    asm("cvt.rna.tf32.f32 %0, %1;" : "=f"(r) : "f"(x));
    return r;
}
__device__ __forceinline__ void mma_tf32(float* c, const float4& a, const float2& b) {
    asm volatile(
        "mma.sync.aligned.m16n8k8.row.col.f32.tf32.tf32.f32 "
        "{%0,%1,%2,%3}, {%4,%5,%6,%7}, {%8,%9}, {%0,%1,%2,%3};"
        : "+f"(c[0]), "+f"(c[1]), "+f"(c[2]), "+f"(c[3])
        : "r"(__float_as_uint(a.x)), "r"(__float_as_uint(a.y)),
          "r"(__float_as_uint(a.z)), "r"(__float_as_uint(a.w)),
          "r"(__float_as_uint(b.x)), "r"(__float_as_uint(b.y)));
}
__device__ __forceinline__ void mma_bf16(float* c, const uint4& a, const uint2& b) {
    asm volatile(
        "mma.sync.aligned.m16n8k16.row.col.f32.bf16.bf16.f32 "
        "{%0,%1,%2,%3}, {%4,%5,%6,%7}, {%8,%9}, {%0,%1,%2,%3};"
        : "+f"(c[0]), "+f"(c[1]), "+f"(c[2]), "+f"(c[3])
        : "r"(a.x), "r"(a.y), "r"(a.z), "r"(a.w), "r"(b.x), "r"(b.y));
}
__device__ __forceinline__ void cp16(void* smem, const void* gmem) {
    unsigned s = (unsigned)__cvta_generic_to_shared(smem);
    asm volatile("cp.async.cg.shared.global [%0], [%1], 16;\n" :: "r"(s), "l"(gmem));
}

// ---------------- 1. weight prep into fragment layouts -----------------------
__global__ void prep_w_kernel(const float* __restrict__ W_lin)
{
    int n = blockIdx.x;                // 0..511
    for (int k = threadIdx.x; k < KPAD; k += blockDim.x) {
        float v = (k < KRAW) ? to_tf32(W_lin[(size_t)n * KRAW + k]) : 0.f;
        int nblk = n >> 3, ki = k >> 3;
        int l = (n & 7) * 4 + ((k & 7) & 3);
        int e = (k & 7) >> 2;
        g_WpadF[((size_t)nblk * 108 + ki) * 64 + l * 2 + e] = v;
    }
}

__global__ void prep_wih_kernel(const float* __restrict__ Wl,
                                const float* __restrict__ Wr,
                                const float* __restrict__ ctypeEmb)
{
    if (blockIdx.x == 0 && threadIdx.x < 512) {
        int ty = threadIdx.x >> 6, c = threadIdx.x & 63;
        g_ct64[threadIdx.x] = (c < 50) ? to_tf32(ctypeEmb[ty * 50 + c]) : 0.f;
    }
    int i = blockIdx.x * blockDim.x + threadIdx.x;
    int ntot = G4 * HID;
    for (int j = i; j < ntot; j += gridDim.x * blockDim.x) {
        int n = j >> 9, k = j & 511;
        int nblk = n >> 3, ki = k >> 3;
        int l = (n & 7) * 4 + ((k & 7) & 3);
        int e = (k & 7) >> 2;
        size_t d = ((size_t)nblk * 64 + ki) * 64 + l * 2 + e;
        g_WihF[0][d] = to_tf32(Wl[j]);
        g_WihF[1][d] = to_tf32(Wr[j]);
    }
}

// ---------------- 2. stage-1 GEMM: fused gather, fragment-packed output ------
// A smem tile 128x36 (row-major, gathered); B smem tile = fragment atoms
// [nblk16][ki4][64].  Epilogue stages through smem and writes g_inF fragments.
#define A1TS 4608                       // 128 x 36
#define B1TS 4096                       // 16 x 4 x 64
#define ST1  (A1TS + B1TS)              // 8704 floats per stage
#define IDX_OFF (2 * ST1)               // int region after 2 stages
#define GSM1 ((2 * ST1 + 640) * 4)      // 72192 B

__global__ __launch_bounds__(256, 2) void gemm1_tc(
    const int* __restrict__ char_idx, const int* __restrict__ ext_idx,
    const int* __restrict__ lbi,      const int* __restrict__ rbi,
    const int* __restrict__ lext,     const int* __restrict__ rext,
    const int* __restrict__ ctype_idx,
    const float* __restrict__ charEmb, const float* __restrict__ extEmb,
    const float* __restrict__ biEmb,   const float* __restrict__ xbiEmb,
    const float* __restrict__ bias)
{
    extern __shared__ float smx[];
    int* si = (int*)(smx + IDX_OFF);
    int side = blockIdx.z;
    float* inF = g_inF[side];

    int tid = threadIdx.x, l = tid & 31, w = tid >> 5;
    int wm = w & 1, wn = w >> 1;
    int m0 = blockIdx.y * 128, n0 = blockIdx.x * 128;

    // stage token indices for this CTA's 128 rows
    if (tid < 128) {
        int t = m0 + tid;
        si[tid]       = char_idx[t];
        si[128 + tid] = ext_idx[t];
        si[256 + tid] = side ? rbi[t]  : lbi[t];
        si[384 + tid] = side ? rext[t] : lext[t];
        si[512 + tid] = ctype_idx[t];
    }
    __syncthreads();

    float acc[4][4][4];
#pragma unroll
    for (int mi = 0; mi < 4; mi++)
#pragma unroll
        for (int nt = 0; nt < 4; nt++)
#pragma unroll
            for (int r = 0; r < 4; r++) acc[mi][nt][r] = 0.f;

    const int NS = KPAD / 32;   // 27

    auto ld_a = [&](float* As, int row, int kg, int k0) {
        int k = k0 + kg;
        const float* src;
        if (k < 200)      src = charEmb + (size_t)si[row] * 200 + k;
        else if (k < 400) src = extEmb  + (size_t)si[128 + row] * 200 + (k - 200);
        else if (k < 600) src = biEmb   + (size_t)si[256 + row] * 200 + (k - 400);
        else if (k < 800) src = xbiEmb  + (size_t)si[384 + row] * 200 + (k - 600);
        else              src = g_ct64 + si[512 + row] * 64 + (k - 800);
        cp16(&As[row * 36 + kg], src);
    };
    auto ld_b = [&](float* Bs, int id, int ks) {  // id 0..1023, 16B chunks
        int f = id * 4;
        int nblk_loc = f >> 8, rem = f & 255;
        int ki_loc = rem >> 6, el = rem & 63;
        cp16(&Bs[f], &g_WpadF[((size_t)((n0 >> 3) + nblk_loc) * 108
                               + (ks * 4 + ki_loc)) * 64 + el]);
    };

    {   // preload stage 0
        float* As = smx; float* Bs = smx + A1TS;
#pragma unroll
        for (int r = 0; r < 4; r++) {
            int id = tid + r * 256;
            ld_a(As, id >> 3, (id & 7) << 2, 0);
            ld_b(Bs, id, 0);
        }
        asm volatile("cp.async.commit_group;\n");
    }

    for (int ks = 0; ks < NS; ks++) {
        if (ks + 1 < NS) {
            int k0 = (ks + 1) * 32;
            float* As = smx + ((ks + 1) & 1) * ST1;
            float* Bs = As + A1TS;
#pragma unroll
            for (int r = 0; r < 4; r++) {
                int id = tid + r * 256;
                ld_a(As, id >> 3, (id & 7) << 2, k0);
                ld_b(Bs, id, ks + 1);
            }
            asm volatile("cp.async.commit_group;\n");
            asm volatile("cp.async.wait_group 1;\n");
        } else {
            asm volatile("cp.async.wait_group 0;\n");
        }
        __syncthreads();

        float* As = smx + (ks & 1) * ST1;
        float* Bs = As + A1TS;
#pragma unroll
        for (int ki = 0; ki < 4; ki++) {
            int kk = ki * 8;
            float4 a[4]; float2 b[4];
#pragma unroll
            for (int mi = 0; mi < 4; mi++) {
                int r0 = wm * 64 + mi * 16 + (l >> 2);
                a[mi].x = As[r0 * 36 + kk + (l & 3)];
                a[mi].y = As[(r0 + 8) * 36 + kk + (l & 3)];
                a[mi].z = As[r0 * 36 + kk + (l & 3) + 4];
                a[mi].w = As[(r0 + 8) * 36 + kk + (l & 3) + 4];
            }
#pragma unroll
            for (int nt = 0; nt < 4; nt++)
                b[nt] = *(const float2*)&Bs[(((wn * 4 + nt) * 4 + ki) * 32 + l) * 2];
#pragma unroll
            for (int mi = 0; mi < 4; mi++)
#pragma unroll
                for (int nt = 0; nt < 4; nt++)
                    mma_tf32(acc[mi][nt], a[mi], b[nt]);
        }
        __syncthreads();
    }

    // ---- epilogue: tanh+bias, stage to smem, write A-fragment layout --------
    float* stg = smx;                  // 128 x 132 staging (67584 B fits)
#pragma unroll
    for (int mi = 0; mi < 4; mi++) {
#pragma unroll
        for (int rh = 0; rh < 2; rh++) {
            int row_loc = wm * 64 + mi * 16 + (l >> 2) + rh * 8;
#pragma unroll
            for (int nt = 0; nt < 4; nt++) {
                int col_loc = wn * 32 + nt * 8 + (l & 3) * 2;
                float2 bv = *(const float2*)&bias[n0 + col_loc];
                float2 v;
                v.x = to_tf32(tanhf(acc[mi][nt][rh * 2 + 0] + bv.x));
                v.y = to_tf32(tanhf(acc[mi][nt][rh * 2 + 1] + bv.y));
                *(float2*)&stg[row_loc * 132 + col_loc] = v;
            }
        }
    }
    __syncthreads();

    // fragment write: warp w owns mblk_loc = w; i = kib_loc 0..15
#pragma unroll
    for (int i = 0; i < 16; i++) {
        int rbase = w * 16, cbase = i * 8;
        float4 v;
        v.x = stg[(rbase + (l >> 2)) * 132 + cbase + (l & 3)];
        v.y = stg[(rbase + (l >> 2) + 8) * 132 + cbase + (l & 3)];
        v.z = stg[(rbase + (l >> 2)) * 132 + cbase + (l & 3) + 4];
        v.w = stg[(rbase + (l >> 2) + 8) * 132 + cbase + (l & 3) + 4];
        *(float4*)&inF[(((size_t)(m0 >> 4) + w) * 64 + ((n0 >> 3) + i)) * 128 + l * 4] = v;
    }
}

// ---------------- 3. stage-2 GEMM: fragment operands -------------------------
// A tile: [mblk8][ki4][128], B tile: [nblk16][ki4][64] -> 8192 floats/stage
#define A2TS 4096
#define B2TS 4096
#define ST2  (A2TS + B2TS)
#define GSM2 (2 * ST2 * 4)              // 65536 B

__global__ __launch_bounds__(256, 2) void gemm2_tc(
    const float* __restrict__ b_ih_l, const float* __restrict__ b_hh_l,
    const float* __restrict__ b_ih_r, const float* __restrict__ b_hh_r)
{
    extern __shared__ float smx[];
    int side = blockIdx.z;
    const float* A  = g_inF[side];
    const float* Bw = g_WihF[side];
    float*       C  = side ? g_xgR : g_xgL;
    const float* b_ih = side ? b_ih_r : b_ih_l;
    const float* b_hh = side ? b_hh_r : b_hh_l;

    int tid = threadIdx.x, l = tid & 31, w = tid >> 5;
    int wm = w & 1, wn = w >> 1;
    int m0 = blockIdx.y * 128, n0 = blockIdx.x * 128;

    float acc[4][4][4];
#pragma unroll
    for (int mi = 0; mi < 4; mi++)
#pragma unroll
        for (int nt = 0; nt < 4; nt++)
#pragma unroll
            for (int r = 0; r < 4; r++) acc[mi][nt][r] = 0.f;

    const int NS = HID / 32;   // 16

    auto ld_a = [&](float* As, int id, int ks) {   // id 0..1023
        int f = id * 4;
        int mblk_loc = f >> 9, rem = f & 511;
        int ki_loc = rem >> 7, el = rem & 127;
        cp16(&As[f], &A[(((size_t)(m0 >> 4) + mblk_loc) * 64
                         + (ks * 4 + ki_loc)) * 128 + el]);
    };
    auto ld_b = [&](float* Bs, int id, int ks) {
        int f = id * 4;
        int nblk_loc = f >> 8, rem = f & 255;
        int ki_loc = rem >> 6, el = rem & 63;
        cp16(&Bs[f], &Bw[(((size_t)(n0 >> 3) + nblk_loc) * 64
                          + (ks * 4 + ki_loc)) * 64 + el]);
    };

    {
        float* As = smx; float* Bs = smx + A2TS;
#pragma unroll
        for (int r = 0; r < 4; r++) {
            int id = tid + r * 256;
            ld_a(As, id, 0);
            ld_b(Bs, id, 0);
        }
        asm volatile("cp.async.commit_group;\n");
    }

    for (int ks = 0; ks < NS; ks++) {
        if (ks + 1 < NS) {
            float* As = smx + ((ks + 1) & 1) * ST2;
            float* Bs = As + A2TS;
#pragma unroll
            for (int r = 0; r < 4; r++) {
                int id = tid + r * 256;
                ld_a(As, id, ks + 1);
                ld_b(Bs, id, ks + 1);
            }
            asm volatile("cp.async.commit_group;\n");
            asm volatile("cp.async.wait_group 1;\n");
        } else {
            asm volatile("cp.async.wait_group 0;\n");
        }
        __syncthreads();

        float* As = smx + (ks & 1) * ST2;
        float* Bs = As + A2TS;
#pragma unroll
        for (int ki = 0; ki < 4; ki++) {
            float4 a[4]; float2 b[4];
#pragma unroll
            for (int mi = 0; mi < 4; mi++)
                a[mi] = *(const float4*)&As[(((wm * 4 + mi) * 4 + ki) * 32 + l) * 4];
#pragma unroll
            for (int nt = 0; nt < 4; nt++)
                b[nt] = *(const float2*)&Bs[(((wn * 4 + nt) * 4 + ki) * 32 + l) * 2];
#pragma unroll
            for (int mi = 0; mi < 4; mi++)
#pragma unroll
                for (int nt = 0; nt < 4; nt++)
                    mma_tf32(acc[mi][nt], a[mi], b[nt]);
        }
        __syncthreads();
    }

#pragma unroll
    for (int mi = 0; mi < 4; mi++) {
#pragma unroll
        for (int rh = 0; rh < 2; rh++) {
            int m = m0 + wm * 64 + mi * 16 + (l >> 2) + rh * 8;
            int s = m & (SS - 1);
            int b = m >> 9;
            float* crow = C + ((size_t)s * BB + b) * G4;
#pragma unroll
            for (int nt = 0; nt < 4; nt++) {
                int col = n0 + wn * 32 + nt * 8 + (l & 3) * 2;
                float2 b1 = *(const float2*)&b_ih[col];
                float2 b2 = *(const float2*)&b_hh[col];
                float2 v;
                v.x = acc[mi][nt][rh * 2 + 0] + b1.x + b2.x;
                v.y = acc[mi][nt][rh * 2 + 1] + b1.y + b2.y;
                *(float2*)&crow[col] = v;
            }
        }
    }
}

// ---------------- 4. reset LSTM state ----------------------------------------
__global__ void init_kernel()
{
    int i = blockIdx.x * blockDim.x + threadIdx.x;
    if (i < 2) g_cnt[i] = 0u;
    unsigned* h = (unsigned*)&g_hbf[0][0][0];
    int n = 2 * 2 * BB * HID / 2;
    for (int j = i; j < n; j += gridDim.x * blockDim.x) h[j] = 0u;
}

// ---------------- 5. persistent bidirectional LSTM (bf16 tensor cores) -------
// 128 CTAs (PROVEN structure), verbatim from the passing R13 kernel.
#define SMB_WH   0
#define SMB_PB   32768
#define SMB_XS   41472
#define SMB_TOT  57856

__global__ __launch_bounds__(256, 1) void lstm_kernel(const float* __restrict__ Whl,
                                                      const float* __restrict__ Whr,
                                                      float* __restrict__ out)
{
    extern __shared__ char smraw[];
    __nv_bfloat16* Wh = (__nv_bfloat16*)(smraw + SMB_WH);
    unsigned* Wh32    = (unsigned*)(smraw + SMB_WH);
    float* Pb  = (float*)(smraw + SMB_PB);
    float* Xs0 = (float*)(smraw + SMB_XS);
    float* Xs1 = (float*)(smraw + SMB_XS + 8192);

    int tid = threadIdx.x;
    int bid = blockIdx.x;
    int dir = bid >> 6;
    int n0  = (bid & 63) << 3;

    const float* Whh = dir ? Whr : Whl;
    const float* xg  = dir ? g_xgR : g_xgL;
    __nv_bfloat16* hb0 = g_hbf[dir][0];
    __nv_bfloat16* hb1 = g_hbf[dir][1];
    unsigned* cnt = &g_cnt[dir];

    for (int id = tid; id < 16384; id += 256) {
        int half = id & 1;
        int e    = (id >> 1) & 1;
        int lane = (id >> 2) & 31;
        int nt   = (id >> 7) & 3;
        int ki   = id >> 9;
        int k    = ki * 16 + e * 8 + (lane & 3) * 2 + half;
        int c    = nt * 8 + (lane >> 2);
        int grow = ((c >> 3) << 9) + n0 + (c & 7);
        Wh[id] = __float2bfloat16_rn(Whh[(size_t)grow * 512 + k]);
    }

    int lane = tid & 31;
    int w    = tid >> 5;
    int mt   = w & 3;
    int kq   = w >> 2;

    float creg[4];
#pragma unroll
    for (int r = 0; r < 4; r++) creg[r] = 0.f;

    {
        int t0 = dir ? (SS - 1) : 0;
        size_t xb = (size_t)t0 * (BB * G4);
        for (int r = 0; r < 2; r++) {
            int id = tid + r * 256;
            int m = id >> 3, seg = (id >> 1) & 3, q = id & 1;
            cp16(&Xs0[(m * 4 + seg) * 8 + q * 4],
                 &xg[xb + (size_t)m * G4 + n0 + seg * 512 + q * 4]);
        }
        asm volatile("cp.async.commit_group;\n");
    }
    __syncthreads();

    int slot17 = (mt * 32 + lane) * 17;

    for (int it = 0; it < SS; it++) {
        int t = dir ? (SS - 1 - it) : it;
        const unsigned* hprev32 = (const unsigned*)((it & 1) ? hb1 : hb0);
        __nv_bfloat16*  hnext   = (it & 1) ? hb0 : hb1;
        float* Xc = (it & 1) ? Xs1 : Xs0;
        float* Xn = (it & 1) ? Xs0 : Xs1;

        float acc[4][4];
#pragma unroll
        for (int nt = 0; nt < 4; nt++)
#pragma unroll
            for (int r = 0; r < 4; r++) acc[nt][r] = 0.f;

        const uint4* ap = (const uint4*)&hprev32[(((kq * 16) * 4 + mt) * 32 + lane) * 4];
#pragma unroll
        for (int kl = 0; kl < 16; kl++) {
            uint4 a = __ldcg(ap + kl * 128);
            int ki = kq * 16 + kl;
#pragma unroll
            for (int nt = 0; nt < 4; nt++) {
                uint2 b = *(const uint2*)&Wh32[((ki * 4 + nt) * 32 + lane) * 2];
                mma_bf16(acc[nt], a, b);
            }
        }

        if (kq) {
#pragma unroll
            for (int nt = 0; nt < 4; nt++)
#pragma unroll
                for (int r = 0; r < 4; r++)
                    Pb[slot17 + nt * 4 + r] = acc[nt][r];
        }
        asm volatile("cp.async.wait_group 0;\n");
        __syncthreads();

        if (!kq) {
#pragma unroll
            for (int rh = 0; rh < 2; rh++) {
                int m = mt * 16 + (lane >> 2) + rh * 8;
                const float* xr = &Xc[m * 32];
                int je = (lane & 3) * 2;
                float hpair[2];
#pragma unroll
                for (int c = 0; c < 2; c++) {
                    int r = rh * 2 + c;
                    int j = je + c;
                    float gi = acc[0][r] + Pb[slot17 + 0 + r]  + xr[j];
                    float gf = acc[1][r] + Pb[slot17 + 4 + r]  + xr[8 + j];
                    float gg = acc[2][r] + Pb[slot17 + 8 + r]  + xr[16 + j];
                    float go = acc[3][r] + Pb[slot17 + 12 + r] + xr[24 + j];
                    float cn = siga(gf) * creg[r] + siga(gi) * tanha(gg);
                    float h  = siga(go) * tanha(cn);
                    creg[r] = cn;
                    hpair[c] = h;
                }
                int kge = n0 + je;
                int ki2 = kge >> 4;
                int ln  = (m & 7) * 4 + ((kge >> 1) & 3);
                int e   = ((m >> 3) & 1) + 2 * ((kge >> 3) & 1);
                unsigned word = (__bfloat16_as_ushort(__float2bfloat16_rn(hpair[0]))) |
                                ((unsigned)__bfloat16_as_ushort(__float2bfloat16_rn(hpair[1])) << 16);
                unsigned* dst = (unsigned*)hnext + ((ki2 * 4 + mt) * 32 + ln) * 4 + e;
                asm volatile("st.global.cg.u32 [%0], %1;" :: "l"(dst), "r"(word));
                float2 ov; ov.x = hpair[0]; ov.y = hpair[1];
                *(float2*)&out[((size_t)m * SS + t) * 1024 + (dir << 9) + n0 + je] = ov;
            }
        }

        if (it + 1 < SS) {
            int tn = dir ? (SS - 2 - it) : (it + 1);
            size_t xb = (size_t)tn * (BB * G4);
            for (int r = 0; r < 2; r++) {
                int id = tid + r * 256;
                int m = id >> 3, seg = (id >> 1) & 3, q = id & 1;
                cp16(&Xn[(m * 4 + seg) * 8 + q * 4],
                     &xg[xb + (size_t)m * G4 + n0 + seg * 512 + q * 4]);
            }
            asm volatile("cp.async.commit_group;\n");

            __syncthreads();
            if (tid == 0) {
                __threadfence();
                atomicAdd(cnt, 1u);
                unsigned tgt = 64u * (unsigned)(it + 1);
                unsigned v;
                while (true) {
                    asm volatile("ld.global.cg.u32 %0, [%1];" : "=r"(v) : "l"(cnt));
                    if (v >= tgt) break;
                    __nanosleep(16);
                }
            }
            __syncthreads();
        }
    }
}

// ---------------- host launch -------------------------------------------------
extern "C" void kernel_launch(void* const* d_in, const int* in_sizes, int n_in,
                              void* d_out, int out_size)
{
    const int*   char_idx  = (const int*)d_in[0];
    const int*   ctype_idx = (const int*)d_in[1];
    const int*   lbi_idx   = (const int*)d_in[2];
    const int*   rbi_idx   = (const int*)d_in[3];
    const int*   ext_idx   = (const int*)d_in[4];
    const int*   lext_idx  = (const int*)d_in[5];
    const int*   rext_idx  = (const int*)d_in[6];
    const float* charEmb   = (const float*)d_in[7];
    const float* ctypeEmb  = (const float*)d_in[8];
    const float* biEmb     = (const float*)d_in[9];
    const float* extEmb    = (const float*)d_in[10];
    const float* extBiEmb  = (const float*)d_in[11];
    const float* W_lin     = (const float*)d_in[12];
    const float* b_lin     = (const float*)d_in[13];
    const float* W_ih_l    = (const float*)d_in[14];
    const float* W_hh_l    = (const float*)d_in[15];
    const float* b_ih_l    = (const float*)d_in[16];
    const float* b_hh_l    = (const float*)d_in[17];
    const float* W_ih_r    = (const float*)d_in[18];
    const float* W_hh_r    = (const float*)d_in[19];
    const float* b_ih_r    = (const float*)d_in[20];
    const float* b_hh_r    = (const float*)d_in[21];
    float* out = (float*)d_out;

    prep_w_kernel<<<512, 128>>>(W_lin);
    prep_wih_kernel<<<256, 512>>>(W_ih_l, W_ih_r, ctypeEmb);

    cudaFuncSetAttribute(gemm1_tc, cudaFuncAttributeMaxDynamicSharedMemorySize, GSM1);
    cudaFuncSetAttribute(gemm2_tc, cudaFuncAttributeMaxDynamicSharedMemorySize, GSM2);

    gemm1_tc<<<dim3(4, 256, 2), 256, GSM1>>>(
        char_idx, ext_idx, lbi_idx, rbi_idx, lext_idx, rext_idx, ctype_idx,
        charEmb, extEmb, biEmb, extBiEmb, b_lin);
    gemm2_tc<<<dim3(16, 256, 2), 256, GSM2>>>(b_ih_l, b_hh_l, b_ih_r, b_hh_r);

    init_kernel<<<64, 256>>>();

    cudaFuncSetAttribute(lstm_kernel, cudaFuncAttributeMaxDynamicSharedMemorySize,
                         SMB_TOT);
    lstm_kernel<<<128, 256, SMB_TOT>>>(W_hh_l, W_hh_r, out);
}